// round 16
// baseline (speedup 1.0000x reference)
#include <cuda_runtime.h>
#include <cuda_bf16.h>
#include <mma.h>
#include <math.h>
#include <stdint.h>

using namespace nvcuda;

// Problem constants (shapes fixed by the dataset)
#define BDIM  2
#define LDIM  2048
#define MDL   1024      // model_dim
#define INNER 2048
#define NST   16        // ssm state n
#define DR    64        // dt rank
#define MROWS (BDIM*LDIM)   // 4096
#define NXZ   (2*INNER)     // 4096
#define NPAR  96            // dr + 2n
#define SPLITK2 8
#define SSEG   16           // scan segments
#define SEGLEN (LDIM/SSEG)  // 128

// ---------------- scratch (static __device__: allocation-free) ----------------
__device__ __align__(16) float g_xz[(size_t)MROWS*NXZ];      // 67 MB
__device__ __align__(16) float g_u[(size_t)MROWS*INNER];     // 33.5 MB
__device__ __align__(16) float g_params[(size_t)MROWS*NPAR]; // 1.5 MB
__device__ __align__(16) float g_ppart[(size_t)SPLITK2*MROWS*NPAR]; // 12.6 MB
__device__ __align__(16) float g_dt[(size_t)MROWS*INNER];    // 33.5 MB
// bf16 split operand buffers
__device__ __align__(16) __nv_bfloat16 g_ah[(size_t)MROWS*MDL];   // A hi (x / d_low)
__device__ __align__(16) __nv_bfloat16 g_al[(size_t)MROWS*MDL];   // A lo
__device__ __align__(16) __nv_bfloat16 g_bh[(size_t)NXZ*MDL];     // B hi (weights)
__device__ __align__(16) __nv_bfloat16 g_bl[(size_t)NXZ*MDL];     // B lo
__device__ __align__(16) __nv_bfloat16 g_wdh[(size_t)INNER*DR];   // W_dt hi
__device__ __align__(16) __nv_bfloat16 g_wdl[(size_t)INNER*DR];   // W_dt lo
__device__ __align__(16) __nv_bfloat16 g_uh[(size_t)MROWS*INNER]; // u hi, later ys hi
__device__ __align__(16) __nv_bfloat16 g_ul[(size_t)MROWS*INNER]; // u lo, later ys lo
// segmented-scan intermediates
__device__ __align__(16) float g_hloc [(size_t)SSEG*NST*MROWS];   // 4 MB
__device__ __align__(16) float g_hin  [(size_t)SSEG*NST*MROWS];   // 4 MB
__device__ __align__(16) float g_sumdt[(size_t)SSEG*MROWS];       // 256 KB

// ---------------- helpers -----------------------------------------------------
__device__ __forceinline__ uint32_t smem_u32(const void* p){
    uint32_t a;
    asm("{ .reg .u64 t; cvta.to.shared.u64 t, %1; cvt.u32.u64 %0, t; }"
        : "=r"(a) : "l"(p));
    return a;
}
__device__ __forceinline__ float softplusf(float x){
    return fmaxf(x, 0.f) + log1pf(__expf(-fabsf(x)));
}
__device__ __forceinline__ void cp16(uint32_t dst, const void* src, int srcbytes){
    asm volatile("cp.async.cg.shared.global [%0], [%1], 16, %2;"
                 :: "r"(dst), "l"(src), "r"(srcbytes) : "memory");
}

// ---------------- bf16-split WMMA GEMM (baseline HMMA path) -------------------
// C[M,N] = (Ah+Al)[M,K] @ (Bh+Bl)[N,K]^T via 3 bf16 MMAs (fp32 accum).
// CTA 128x128, BK=32, 512 threads: 16 warps (4M x 4N), warp tile 32x32.
// Whole chunk's fragments (16 x 4 = 64 regs) + acc (32) fit under the 128-reg
// cap -> no per-kk load/MMA dependency bubble, no spills.
// Split-K via blockIdx.z: pointers advance z*Kloop, C advances z*cSlice.
// EPI: 0 = plain store, 1 = softplus(acc + bias[n]) staged through SMEM.
#define BK     32
#define LDT    40                    // padded row length in bf16 (conflict-free)
#define TILE_E (128*LDT)             // 5120 bf16 per tile
#define STAGE_E (4*TILE_E)           // Ah,Al,Bh,Bl
#define GEMM_SMEM (2*STAGE_E*2)      // 81920 bytes (also >= 64KB EPI staging)
#define GTHREADS 512

template<int EPI>
__global__ void __launch_bounds__(GTHREADS, 1) gemm_wmma(
    const __nv_bfloat16* __restrict__ Ah, const __nv_bfloat16* __restrict__ Al,
    const __nv_bfloat16* __restrict__ Bh, const __nv_bfloat16* __restrict__ Bl,
    float* __restrict__ C, int ldc, int N, int Kloop, int lda,
    size_t cSlice, const float* __restrict__ bias)
{
    extern __shared__ __nv_bfloat16 sm[];
    const int tid  = threadIdx.x;
    const int wid  = tid >> 5, lane = tid & 31;
    const int bm   = blockIdx.y * 128, bn = blockIdx.x * 128;
    const int wm   = wid & 3, wn = wid >> 2;      // 4 x 4 warp grid
    const uint32_t smb = smem_u32(sm);

    const size_t koff = (size_t)blockIdx.z * Kloop;
    Ah += koff; Al += koff; Bh += koff; Bl += koff;
    C  += (size_t)blockIdx.z * cSlice;

    wmma::fragment<wmma::accumulator,16,16,16,float> acc[2][2];
    #pragma unroll
    for (int i = 0; i < 2; i++)
        #pragma unroll
        for (int j = 0; j < 2; j++) wmma::fill_fragment(acc[i][j], 0.f);

    const int nch = Kloop / BK;

    // stage loader: 4 tiles x 128 rows x 4 16B-units; 4 cp.async per thread
    auto load_stage = [&](int s, int c){
        const int kof = c * BK;
        const uint32_t sbase = smb + (uint32_t)s * STAGE_E * 2;
        #pragma unroll
        for (int t = 0; t < 4; t++) {
            int i   = tid + t * GTHREADS;   // 0..2047
            int tl  = i >> 9;               // 0..3: Ah,Al,Bh,Bl
            int row = (i >> 2) & 127;
            int un  = i & 3;                // 16B unit within the 32-elem chunk
            const __nv_bfloat16* src;
            int ok = 16;
            if      (tl == 0) src = Ah + (size_t)(bm + row) * lda + kof + un * 8;
            else if (tl == 1) src = Al + (size_t)(bm + row) * lda + kof + un * 8;
            else {
                const __nv_bfloat16* Bs = (tl == 2) ? Bh : Bl;
                if (bn + row < N) src = Bs + (size_t)(bn + row) * lda + kof + un * 8;
                else { src = Bs; ok = 0; }
            }
            uint32_t dst = sbase + (uint32_t)(tl * TILE_E + row * LDT + un * 8) * 2;
            cp16(dst, src, ok);
        }
        asm volatile("cp.async.commit_group;" ::: "memory");
    };

    load_stage(0, 0);
    for (int c = 0; c < nch; c++) {
        if (c + 1 < nch) {
            load_stage((c + 1) & 1, c + 1);
            asm volatile("cp.async.wait_group 1;" ::: "memory");
        } else {
            asm volatile("cp.async.wait_group 0;" ::: "memory");
        }
        __syncthreads();

        const __nv_bfloat16* st = sm + (c & 1) * STAGE_E;
        // load ALL fragments for the whole chunk (both kk halves) up front
        wmma::fragment<wmma::matrix_a,16,16,16,__nv_bfloat16,wmma::row_major> fah[2][2], fal[2][2];
        wmma::fragment<wmma::matrix_b,16,16,16,__nv_bfloat16,wmma::col_major> fbh[2][2], fbl[2][2];
        #pragma unroll
        for (int kk = 0; kk < 2; kk++) {
            #pragma unroll
            for (int i = 0; i < 2; i++) {
                wmma::load_matrix_sync(fah[kk][i], st + (wm*32 + i*16)*LDT + kk*16, LDT);
                wmma::load_matrix_sync(fal[kk][i], st + TILE_E + (wm*32 + i*16)*LDT + kk*16, LDT);
            }
            #pragma unroll
            for (int j = 0; j < 2; j++) {
                wmma::load_matrix_sync(fbh[kk][j], st + 2*TILE_E + (wn*32 + j*16)*LDT + kk*16, LDT);
                wmma::load_matrix_sync(fbl[kk][j], st + 3*TILE_E + (wn*32 + j*16)*LDT + kk*16, LDT);
            }
        }
        #pragma unroll
        for (int kk = 0; kk < 2; kk++)
            #pragma unroll
            for (int i = 0; i < 2; i++)
                #pragma unroll
                for (int j = 0; j < 2; j++) {
                    wmma::mma_sync(acc[i][j], fah[kk][i], fbh[kk][j], acc[i][j]);
                    wmma::mma_sync(acc[i][j], fah[kk][i], fbl[kk][j], acc[i][j]);
                    wmma::mma_sync(acc[i][j], fal[kk][i], fbh[kk][j], acc[i][j]);
                }
        __syncthreads();
    }

    if (EPI == 0) {
        #pragma unroll
        for (int i = 0; i < 2; i++)
            #pragma unroll
            for (int j = 0; j < 2; j++) {
                int col = bn + wn*32 + j*16;
                if (col < N)
                    wmma::store_matrix_sync(
                        C + (size_t)(bm + wm*32 + i*16) * ldc + col,
                        acc[i][j], ldc, wmma::mem_row_major);
            }
    } else {
        // stage 32x32 per warp in smem, apply bias+softplus, coalesced store
        float* stg = (float*)sm + wid * 1024;
        #pragma unroll
        for (int i = 0; i < 2; i++)
            #pragma unroll
            for (int j = 0; j < 2; j++)
                wmma::store_matrix_sync(stg + i*16*32 + j*16, acc[i][j], 32,
                                        wmma::mem_row_major);
        __syncwarp();
        const int r0 = bm + wm*32;
        const int c0 = bn + wn*32;
        #pragma unroll
        for (int idx = lane; idx < 256; idx += 32) {
            int r  = idx >> 3;
            int cq = (idx & 7) * 4;
            float4 v = *(float4*)&stg[r*32 + cq];
            v.x = softplusf(v.x + bias[c0 + cq + 0]);
            v.y = softplusf(v.y + bias[c0 + cq + 1]);
            v.z = softplusf(v.z + bias[c0 + cq + 2]);
            v.w = softplusf(v.w + bias[c0 + cq + 3]);
            *(float4*)&C[(size_t)(r0 + r) * ldc + c0 + cq] = v;
        }
    }
}

// ---------------- split-K reduce for params GEMM ------------------------------
__global__ void reduce_params_kernel()
{
    int i = blockIdx.x * blockDim.x + threadIdx.x;
    if (i >= MROWS * NPAR) return;
    float s = 0.f;
    #pragma unroll
    for (int z = 0; z < SPLITK2; z++)
        s += g_ppart[(size_t)z * MROWS * NPAR + i];
    g_params[i] = s;
}

// ---------------- fp32 -> bf16 hi/lo split (vectorized) ----------------------
__global__ void split_flat4(const float4* __restrict__ src,
                            __nv_bfloat162* __restrict__ h,
                            __nv_bfloat162* __restrict__ l, int n4)
{
    int i = blockIdx.x * blockDim.x + threadIdx.x;
    if (i >= n4) return;
    float4 v = src[i];
    __nv_bfloat162 h0 = __floats2bfloat162_rn(v.x, v.y);
    __nv_bfloat162 h1 = __floats2bfloat162_rn(v.z, v.w);
    float rx = v.x - __bfloat162float(h0.x);
    float ry = v.y - __bfloat162float(h0.y);
    float rz = v.z - __bfloat162float(h1.x);
    float rw = v.w - __bfloat162float(h1.y);
    h[i*2]   = h0;  h[i*2+1] = h1;
    l[i*2]   = __floats2bfloat162_rn(rx, ry);
    l[i*2+1] = __floats2bfloat162_rn(rz, rw);
}

// d_low: rows of g_params (stride NPAR), first DR cols -> compact [MROWS x DR]
__global__ void split_dlow4(const float* __restrict__ src,
                            __nv_bfloat162* __restrict__ h,
                            __nv_bfloat162* __restrict__ l)
{
    int i = blockIdx.x * blockDim.x + threadIdx.x;   // n4 = MROWS*DR/4
    if (i >= MROWS * DR / 4) return;
    int r = i >> 4, c = (i & 15) * 4;
    float4 v = *(const float4*)&src[(size_t)r * NPAR + c];
    __nv_bfloat162 h0 = __floats2bfloat162_rn(v.x, v.y);
    __nv_bfloat162 h1 = __floats2bfloat162_rn(v.z, v.w);
    float rx = v.x - __bfloat162float(h0.x);
    float ry = v.y - __bfloat162float(h0.y);
    float rz = v.z - __bfloat162float(h1.x);
    float rw = v.w - __bfloat162float(h1.y);
    h[i*2]   = h0;  h[i*2+1] = h1;
    l[i*2]   = __floats2bfloat162_rn(rx, ry);
    l[i*2+1] = __floats2bfloat162_rn(rz, rw);
}

// ---------------- depthwise causal conv (k=4) + SiLU (+ bf16 split) ----------
// 8 timesteps per thread: carry x[t-1..t-3] in registers (loads/output ~1.4 vs 4).
#define CONVT 8
__global__ void conv_silu_kernel(const float* __restrict__ conv_w)
{
    int i = blockIdx.x * blockDim.x + threadIdx.x;   // over (MROWS/CONVT)*INNER
    if (i >= MROWS / CONVT * INNER) return;
    int d  = i & (INNER - 1);
    int mb = i >> 11;                 // 0..511
    int m0 = mb * CONVT;
    int t0 = m0 & (LDIM - 1);
    float w0 = conv_w[d*4+0], w1 = conv_w[d*4+1];
    float w2 = conv_w[d*4+2], w3 = conv_w[d*4+3];
    const float* col = g_xz + (size_t)m0 * NXZ + d;
    float xm1, xm2, xm3;
    if (t0 == 0) { xm1 = xm2 = xm3 = 0.f; }
    else { xm1 = col[-NXZ]; xm2 = col[-2*NXZ]; xm3 = col[-3*NXZ]; }
    #pragma unroll
    for (int tt = 0; tt < CONVT; tt++) {
        float xc  = col[tt * NXZ];
        float acc = xc * w3;
        acc = fmaf(xm1, w2, acc);
        acc = fmaf(xm2, w1, acc);
        acc = fmaf(xm3, w0, acc);
        float s = acc * __fdividef(1.f, 1.f + __expf(-acc));
        int idx = (m0 + tt) * INNER + d;
        g_u[idx] = s;
        __nv_bfloat16 hh = __float2bfloat16(s);
        g_uh[idx] = hh;
        g_ul[idx] = __float2bfloat16(s - __bfloat162float(hh));
        xm3 = xm2; xm2 = xm1; xm1 = xc;
    }
}

// ---------------- segmented SSM scan ------------------------------------------
#define SCHUNK 16

__global__ void __launch_bounds__(128) scanA_kernel(const float* __restrict__ logA)
{
    __shared__ float s_u [SCHUNK*128];
    __shared__ float s_dt[SCHUNK*128];
    __shared__ float s_b [SCHUNK*16];

    const int tid = threadIdx.x;
    const int b   = blockIdx.y;
    const int seg = blockIdx.z;
    const int d0  = blockIdx.x * 128;
    const int d   = d0 + tid;
    const int bd  = b * INNER + d;

    float a[NST];
    bool fast = true;
    #pragma unroll
    for (int n = 0; n < NST; n++) {
        a[n] = -__expf(logA[d * NST + n]);
        fast = fast && (fabsf(a[n] + (float)(n + 1)) <= 2e-5f * (float)(n + 1));
    }
    float h[NST];
    #pragma unroll
    for (int n = 0; n < NST; n++) h[n] = 0.f;
    float sumdt = 0.f;

    for (int t0 = 0; t0 < SEGLEN; t0 += SCHUNK) {
        const int rowbase = b * LDIM + seg * SEGLEN + t0;
        #pragma unroll
        for (int r = 0; r < 4; r++) {
            int j = tid + r * 128;
            int row = j >> 5;
            int c   = (j & 31) * 4;
            int gidx = (rowbase + row) * INNER + d0 + c;
            *(float4*)&s_u [row*128 + c] = *(const float4*)&g_u [gidx];
            *(float4*)&s_dt[row*128 + c] = *(const float4*)&g_dt[gidx];
        }
        if (tid < 64) {
            int row = tid >> 2;
            int c   = (tid & 3) * 4;
            *(float4*)&s_b[row*16 + c] =
                *(const float4*)&g_params[(rowbase + row) * NPAR + DR + c];
        }
        __syncthreads();

        if (fast) {
            #pragma unroll 4
            for (int tt = 0; tt < SCHUNK; tt++) {
                float dtv = s_dt[tt*128 + tid];
                float du  = dtv * s_u[tt*128 + tid];
                float e1  = __expf(-dtv);
                float dec = e1;
                sumdt += dtv;
                #pragma unroll
                for (int n = 0; n < NST; n++) {
                    h[n] = fmaf(dec, h[n], du * s_b[tt*16 + n]);
                    dec *= e1;
                }
            }
        } else {
            for (int tt = 0; tt < SCHUNK; tt++) {
                float dtv = s_dt[tt*128 + tid];
                float du  = dtv * s_u[tt*128 + tid];
                sumdt += dtv;
                #pragma unroll
                for (int n = 0; n < NST; n++)
                    h[n] = fmaf(__expf(dtv * a[n]), h[n], du * s_b[tt*16 + n]);
            }
        }
        __syncthreads();
    }

    #pragma unroll
    for (int n = 0; n < NST; n++)
        g_hloc[((size_t)seg * NST + n) * MROWS + bd] = h[n];
    g_sumdt[(size_t)seg * MROWS + bd] = sumdt;
}

__global__ void __launch_bounds__(128) scan_combine(const float* __restrict__ logA)
{
    const int bd = blockIdx.x * 128 + threadIdx.x;   // 0..4095
    const int d  = bd & (INNER - 1);
    float a[NST];
    #pragma unroll
    for (int n = 0; n < NST; n++) a[n] = -__expf(logA[d * NST + n]);
    float h[NST];
    #pragma unroll
    for (int n = 0; n < NST; n++) h[n] = 0.f;
    for (int s = 0; s < SSEG; s++) {
        #pragma unroll
        for (int n = 0; n < NST; n++)
            g_hin[((size_t)s * NST + n) * MROWS + bd] = h[n];
        float sd = g_sumdt[(size_t)s * MROWS + bd];
        #pragma unroll
        for (int n = 0; n < NST; n++)
            h[n] = fmaf(__expf(a[n] * sd), h[n],
                        g_hloc[((size_t)s * NST + n) * MROWS + bd]);
    }
}

__global__ void __launch_bounds__(128) scanB_kernel(
    const float* __restrict__ logA, const float* __restrict__ Dvec)
{
    __shared__ float s_u [SCHUNK*128];
    __shared__ float s_dt[SCHUNK*128];
    __shared__ float s_g [SCHUNK*128];
    __shared__ float s_bc[SCHUNK*32];

    const int tid = threadIdx.x;
    const int b   = blockIdx.y;
    const int seg = blockIdx.z;
    const int d0  = blockIdx.x * 128;
    const int d   = d0 + tid;
    const int bd  = b * INNER + d;

    float a[NST];
    bool fast = true;
    #pragma unroll
    for (int n = 0; n < NST; n++) {
        a[n] = -__expf(logA[d * NST + n]);
        fast = fast && (fabsf(a[n] + (float)(n + 1)) <= 2e-5f * (float)(n + 1));
    }
    const float Dd = Dvec[d];
    float h[NST];
    #pragma unroll
    for (int n = 0; n < NST; n++)
        h[n] = g_hin[((size_t)seg * NST + n) * MROWS + bd];

    for (int t0 = 0; t0 < SEGLEN; t0 += SCHUNK) {
        const int rowbase = b * LDIM + seg * SEGLEN + t0;
        #pragma unroll
        for (int r = 0; r < 4; r++) {
            int j = tid + r * 128;
            int row = j >> 5;
            int c   = (j & 31) * 4;
            int gidx = (rowbase + row) * INNER + d0 + c;
            *(float4*)&s_u [row*128 + c] = *(const float4*)&g_u [gidx];
            *(float4*)&s_dt[row*128 + c] = *(const float4*)&g_dt[gidx];
            *(float4*)&s_g [row*128 + c] =
                *(const float4*)&g_xz[(size_t)(rowbase + row) * NXZ + INNER + d0 + c];
        }
        {
            int row = tid >> 3;
            int c   = (tid & 7) * 4;
            *(float4*)&s_bc[row*32 + c] =
                *(const float4*)&g_params[(rowbase + row) * NPAR + DR + c];
        }
        __syncthreads();

        if (fast) {
            #pragma unroll 4
            for (int tt = 0; tt < SCHUNK; tt++) {
                float dtv = s_dt[tt*128 + tid];
                float uu  = s_u [tt*128 + tid];
                float du  = dtv * uu;
                float e1  = __expf(-dtv);
                float dec = e1;
                float y = 0.f;
                #pragma unroll
                for (int n = 0; n < NST; n++) {
                    h[n] = fmaf(dec, h[n], du * s_bc[tt*32 + n]);
                    y    = fmaf(h[n], s_bc[tt*32 + 16 + n], y);
                    dec *= e1;
                }
                float g  = s_g[tt*128 + tid];
                float sg = g * __fdividef(1.f, 1.f + __expf(-g));
                float v  = fmaf(uu, Dd, y) * sg;
                int idx  = (rowbase + tt) * INNER + d;
                __nv_bfloat16 hh = __float2bfloat16(v);
                g_uh[idx] = hh;
                g_ul[idx] = __float2bfloat16(v - __bfloat162float(hh));
            }
        } else {
            for (int tt = 0; tt < SCHUNK; tt++) {
                float dtv = s_dt[tt*128 + tid];
                float uu  = s_u [tt*128 + tid];
                float du  = dtv * uu;
                float y = 0.f;
                #pragma unroll
                for (int n = 0; n < NST; n++) {
                    h[n] = fmaf(__expf(dtv * a[n]), h[n], du * s_bc[tt*32 + n]);
                    y    = fmaf(h[n], s_bc[tt*32 + 16 + n], y);
                }
                float g  = s_g[tt*128 + tid];
                float sg = g * __fdividef(1.f, 1.f + __expf(-g));
                float v  = fmaf(uu, Dd, y) * sg;
                int idx  = (rowbase + tt) * INNER + d;
                __nv_bfloat16 hh = __float2bfloat16(v);
                g_uh[idx] = hh;
                g_ul[idx] = __float2bfloat16(v - __bfloat162float(hh));
            }
        }
        __syncthreads();
    }
}

// ---------------- launcher ----------------------------------------------------
extern "C" void kernel_launch(void* const* d_in, const int* in_sizes, int n_in,
                              void* d_out, int out_size)
{
    const float* x      = (const float*)d_in[0];  // (2,2048,1024)
    const float* W_in   = (const float*)d_in[1];  // (4096,1024)
    const float* conv_w = (const float*)d_in[2];  // (2048,4)
    const float* W_ssm  = (const float*)d_in[3];  // (96,2048)
    const float* W_dt   = (const float*)d_in[4];  // (2048,64)
    const float* b_dt   = (const float*)d_in[5];  // (2048,)
    const float* logA   = (const float*)d_in[6];  // (2048,16)
    const float* Dv     = (const float*)d_in[7];  // (2048,)
    const float* W_out  = (const float*)d_in[8];  // (1024,2048)
    float* out = (float*)d_out;

    float *xz, *params, *ppart, *dtb;
    __nv_bfloat16 *ah, *al, *bh, *bl, *wdh, *wdl, *uh, *ul;
    cudaGetSymbolAddress((void**)&xz,     g_xz);
    cudaGetSymbolAddress((void**)&params, g_params);
    cudaGetSymbolAddress((void**)&ppart,  g_ppart);
    cudaGetSymbolAddress((void**)&dtb,    g_dt);
    cudaGetSymbolAddress((void**)&ah,  g_ah);
    cudaGetSymbolAddress((void**)&al,  g_al);
    cudaGetSymbolAddress((void**)&bh,  g_bh);
    cudaGetSymbolAddress((void**)&bl,  g_bl);
    cudaGetSymbolAddress((void**)&wdh, g_wdh);
    cudaGetSymbolAddress((void**)&wdl, g_wdl);
    cudaGetSymbolAddress((void**)&uh,  g_uh);
    cudaGetSymbolAddress((void**)&ul,  g_ul);

    cudaFuncSetAttribute(gemm_wmma<0>,
        cudaFuncAttributeMaxDynamicSharedMemorySize, GEMM_SMEM);
    cudaFuncSetAttribute(gemm_wmma<1>,
        cudaFuncAttributeMaxDynamicSharedMemorySize, GEMM_SMEM);

    // 0-2) splits (x, W_in, W_dt) — gemm1 lands at launch idx 3 for ncu
    split_flat4<<<(MROWS*MDL/4 + 255)/256, 256>>>(
        (const float4*)x, (__nv_bfloat162*)ah, (__nv_bfloat162*)al, MROWS*MDL/4);
    split_flat4<<<(NXZ*MDL/4 + 255)/256, 256>>>(
        (const float4*)W_in, (__nv_bfloat162*)bh, (__nv_bfloat162*)bl, NXZ*MDL/4);
    split_flat4<<<(INNER*DR/4 + 255)/256, 256>>>(
        (const float4*)W_dt, (__nv_bfloat162*)wdh, (__nv_bfloat162*)wdl, INNER*DR/4);

    // 3) xz = x @ W_in^T  (M=4096, N=4096, K=1024)
    gemm_wmma<0><<<dim3(NXZ/128, MROWS/128, 1), GTHREADS, GEMM_SMEM>>>(
        ah, al, bh, bl, xz, NXZ, NXZ, MDL, MDL, 0, nullptr);

    // 4) depthwise causal conv + silu -> u (fp32 + bf16 split)
    conv_silu_kernel<<<(MROWS/CONVT*INNER + 255)/256, 256>>>(conv_w);

    // 5) split W_ssm (reuses bh/bl)
    split_flat4<<<(NPAR*INNER/4 + 255)/256, 256>>>(
        (const float4*)W_ssm, (__nv_bfloat162*)bh, (__nv_bfloat162*)bl, NPAR*INNER/4);

    // 6-7) params = u @ W_ssm^T  (M=4096, N=96, K=2048), split-K=8 + reduce
    gemm_wmma<0><<<dim3(1, MROWS/128, SPLITK2), GTHREADS, GEMM_SMEM>>>(
        uh, ul, bh, bl, ppart, NPAR, NPAR, INNER/SPLITK2, INNER,
        (size_t)MROWS*NPAR, nullptr);
    reduce_params_kernel<<<(MROWS*NPAR + 255)/256, 256>>>();

    // 8) split d_low (params[:, :64] -> ah/al compact [4096 x 64])
    split_dlow4<<<(MROWS*DR/4 + 255)/256, 256>>>(
        params, (__nv_bfloat162*)ah, (__nv_bfloat162*)al);

    // 9) dt = softplus(d_low @ W_dt^T + b_dt)  (M=4096, N=2048, K=64)
    gemm_wmma<1><<<dim3(INNER/128, MROWS/128, 1), GTHREADS, GEMM_SMEM>>>(
        ah, al, wdh, wdl, dtb, INNER, INNER, DR, DR, 0, b_dt);

    // 10-12) segmented SSM scan (S=16): passA, combine, passB
    scanA_kernel<<<dim3(INNER/128, BDIM, SSEG), 128>>>(logA);
    scan_combine<<<MROWS/128, 128>>>(logA);
    scanB_kernel<<<dim3(INNER/128, BDIM, SSEG), 128>>>(logA, Dv);

    // 13) split W_out (reuses bh/bl)
    split_flat4<<<(MDL*INNER/4 + 255)/256, 256>>>(
        (const float4*)W_out, (__nv_bfloat162*)bh, (__nv_bfloat162*)bl, MDL*INNER/4);

    // 14) out = ys @ W_out^T  (M=4096, N=1024, K=2048)
    gemm_wmma<0><<<dim3(MDL/128, MROWS/128, 1), GTHREADS, GEMM_SMEM>>>(
        uh, ul, bh, bl, out, MDL, MDL, INNER, INNER, 0, nullptr);
}

// round 17
// speedup vs baseline: 1.2806x; 1.2806x over previous
#include <cuda_runtime.h>
#include <cuda_bf16.h>
#include <mma.h>
#include <math.h>
#include <stdint.h>

using namespace nvcuda;

// Problem constants (shapes fixed by the dataset)
#define BDIM  2
#define LDIM  2048
#define MDL   1024      // model_dim
#define INNER 2048
#define NST   16        // ssm state n
#define DR    64        // dt rank
#define MROWS (BDIM*LDIM)   // 4096
#define NXZ   (2*INNER)     // 4096
#define NPAR  96            // dr + 2n
#define SPLITK2 8
#define SSEG   16           // scan segments
#define SEGLEN (LDIM/SSEG)  // 128

// ---------------- scratch (static __device__: allocation-free) ----------------
__device__ __align__(16) float g_xz[(size_t)MROWS*NXZ];      // 67 MB
__device__ __align__(16) float g_u[(size_t)MROWS*INNER];     // 33.5 MB
__device__ __align__(16) float g_params[(size_t)MROWS*NPAR]; // 1.5 MB
__device__ __align__(16) float g_ppart[(size_t)SPLITK2*MROWS*NPAR]; // 12.6 MB
__device__ __align__(16) float g_dt[(size_t)MROWS*INNER];    // 33.5 MB
// bf16 split operand buffers
__device__ __align__(16) __nv_bfloat16 g_ah[(size_t)MROWS*MDL];   // A hi (x / d_low)
__device__ __align__(16) __nv_bfloat16 g_al[(size_t)MROWS*MDL];   // A lo
__device__ __align__(16) __nv_bfloat16 g_bh[(size_t)NXZ*MDL];     // B hi (weights)
__device__ __align__(16) __nv_bfloat16 g_bl[(size_t)NXZ*MDL];     // B lo
__device__ __align__(16) __nv_bfloat16 g_wdh[(size_t)INNER*DR];   // W_dt hi
__device__ __align__(16) __nv_bfloat16 g_wdl[(size_t)INNER*DR];   // W_dt lo
__device__ __align__(16) __nv_bfloat16 g_uh[(size_t)MROWS*INNER]; // u hi, later ys hi
__device__ __align__(16) __nv_bfloat16 g_ul[(size_t)MROWS*INNER]; // u lo, later ys lo
// segmented-scan intermediates
__device__ __align__(16) float g_hloc [(size_t)SSEG*NST*MROWS];   // 4 MB
__device__ __align__(16) float g_hin  [(size_t)SSEG*NST*MROWS];   // 4 MB
__device__ __align__(16) float g_sumdt[(size_t)SSEG*MROWS];       // 256 KB

// ---------------- helpers -----------------------------------------------------
__device__ __forceinline__ uint32_t smem_u32(const void* p){
    uint32_t a;
    asm("{ .reg .u64 t; cvta.to.shared.u64 t, %1; cvt.u32.u64 %0, t; }"
        : "=r"(a) : "l"(p));
    return a;
}
__device__ __forceinline__ float softplusf(float x){
    return fmaxf(x, 0.f) + log1pf(__expf(-fabsf(x)));
}
__device__ __forceinline__ void cp16(uint32_t dst, const void* src, int srcbytes){
    asm volatile("cp.async.cg.shared.global [%0], [%1], 16, %2;"
                 :: "r"(dst), "l"(src), "r"(srcbytes) : "memory");
}

// ---------------- bf16-split WMMA GEMM (baseline HMMA path) -------------------
// C[M,N] = (Ah+Al)[M,K] @ (Bh+Bl)[N,K]^T via 3 bf16 MMAs (fp32 accum).
// CTA 128x128, BK=32, 8 warps (4 M x 2 N), warp tile 32x64 (2x4 wmma 16x16).
// __launch_bounds__(256,2): 2 CTAs/SM. Inner loop interleaves fragment loads
// with the three MMA terms so MMAs start after ~half the LDSM and fbh/fbl
// register lifetimes don't overlap.
// Split-K via blockIdx.z: pointers advance z*Kloop, C advances z*cSlice.
// EPI: 0 = plain store, 1 = softplus(acc + bias[n]) staged through SMEM.
#define BK     32
#define LDT    40                    // padded row length in bf16
#define TILE_E (128*LDT)             // 5120 bf16 per tile
#define STAGE_E (4*TILE_E)           // Ah,Al,Bh,Bl
#define GEMM_SMEM (2*STAGE_E*2)      // 81920 bytes (also >= 64KB EPI staging)

template<int EPI>
__global__ void __launch_bounds__(256, 2) gemm_wmma(
    const __nv_bfloat16* __restrict__ Ah, const __nv_bfloat16* __restrict__ Al,
    const __nv_bfloat16* __restrict__ Bh, const __nv_bfloat16* __restrict__ Bl,
    float* __restrict__ C, int ldc, int N, int Kloop, int lda,
    size_t cSlice, const float* __restrict__ bias)
{
    extern __shared__ __nv_bfloat16 sm[];
    const int tid  = threadIdx.x;
    const int wid  = tid >> 5, lane = tid & 31;
    const int bm   = blockIdx.y * 128, bn = blockIdx.x * 128;
    const int wm   = wid & 3, wn = wid >> 2;
    const uint32_t smb = smem_u32(sm);

    const size_t koff = (size_t)blockIdx.z * Kloop;
    Ah += koff; Al += koff; Bh += koff; Bl += koff;
    C  += (size_t)blockIdx.z * cSlice;

    wmma::fragment<wmma::accumulator,16,16,16,float> acc[2][4];
    #pragma unroll
    for (int i = 0; i < 2; i++)
        #pragma unroll
        for (int j = 0; j < 4; j++) wmma::fill_fragment(acc[i][j], 0.f);

    const int nch = Kloop / BK;

    // stage loader: 4 tiles x 128 rows x 2 16B-units; 8 cp.async per thread
    auto load_stage = [&](int s, int c){
        const int kof = c * BK;
        const uint32_t sbase = smb + (uint32_t)s * STAGE_E * 2;
        #pragma unroll
        for (int t = 0; t < 8; t++) {
            int i   = tid + t * 256;        // 0..2047
            int tl  = i >> 9;               // 0..3: Ah,Al,Bh,Bl
            int row = (i >> 2) & 127;
            int un  = i & 3;                // 16B unit within the 32-elem chunk
            const __nv_bfloat16* src;
            int ok = 16;
            if      (tl == 0) src = Ah + (size_t)(bm + row) * lda + kof + un * 8;
            else if (tl == 1) src = Al + (size_t)(bm + row) * lda + kof + un * 8;
            else {
                const __nv_bfloat16* Bs = (tl == 2) ? Bh : Bl;
                if (bn + row < N) src = Bs + (size_t)(bn + row) * lda + kof + un * 8;
                else { src = Bs; ok = 0; }
            }
            uint32_t dst = sbase + (uint32_t)(tl * TILE_E + row * LDT + un * 8) * 2;
            cp16(dst, src, ok);
        }
        asm volatile("cp.async.commit_group;" ::: "memory");
    };

    load_stage(0, 0);
    for (int c = 0; c < nch; c++) {
        if (c + 1 < nch) {
            load_stage((c + 1) & 1, c + 1);
            asm volatile("cp.async.wait_group 1;" ::: "memory");
        } else {
            asm volatile("cp.async.wait_group 0;" ::: "memory");
        }
        __syncthreads();

        const __nv_bfloat16* st = sm + (c & 1) * STAGE_E;
        #pragma unroll
        for (int kk = 0; kk < BK; kk += 16) {
            wmma::fragment<wmma::matrix_a,16,16,16,__nv_bfloat16,wmma::row_major> fah[2], fal[2];
            wmma::fragment<wmma::matrix_b,16,16,16,__nv_bfloat16,wmma::col_major> fbh[4], fbl[4];
            // term 1: Ah·Bh — start MMAs after only fah+fbh are in
            #pragma unroll
            for (int i = 0; i < 2; i++)
                wmma::load_matrix_sync(fah[i], st + (wm*32 + i*16)*LDT + kk, LDT);
            #pragma unroll
            for (int j = 0; j < 4; j++)
                wmma::load_matrix_sync(fbh[j], st + 2*TILE_E + (wn*64 + j*16)*LDT + kk, LDT);
            #pragma unroll
            for (int i = 0; i < 2; i++)
                #pragma unroll
                for (int j = 0; j < 4; j++)
                    wmma::mma_sync(acc[i][j], fah[i], fbh[j], acc[i][j]);
            // term 2: Al·Bh — fal loaded while term-1 MMAs drain
            #pragma unroll
            for (int i = 0; i < 2; i++)
                wmma::load_matrix_sync(fal[i], st + TILE_E + (wm*32 + i*16)*LDT + kk, LDT);
            #pragma unroll
            for (int i = 0; i < 2; i++)
                #pragma unroll
                for (int j = 0; j < 4; j++)
                    wmma::mma_sync(acc[i][j], fal[i], fbh[j], acc[i][j]);
            // term 3: Ah·Bl — fbl loaded last (fbh lifetime ended)
            #pragma unroll
            for (int j = 0; j < 4; j++)
                wmma::load_matrix_sync(fbl[j], st + 3*TILE_E + (wn*64 + j*16)*LDT + kk, LDT);
            #pragma unroll
            for (int i = 0; i < 2; i++)
                #pragma unroll
                for (int j = 0; j < 4; j++)
                    wmma::mma_sync(acc[i][j], fah[i], fbl[j], acc[i][j]);
        }
        __syncthreads();
    }

    if (EPI == 0) {
        #pragma unroll
        for (int i = 0; i < 2; i++)
            #pragma unroll
            for (int j = 0; j < 4; j++) {
                int col = bn + wn*64 + j*16;
                if (col < N)
                    wmma::store_matrix_sync(
                        C + (size_t)(bm + wm*32 + i*16) * ldc + col,
                        acc[i][j], ldc, wmma::mem_row_major);
            }
    } else {
        // stage 32x64 per warp in smem, apply bias+softplus, coalesced store
        float* stg = (float*)sm + wid * 2048;
        #pragma unroll
        for (int i = 0; i < 2; i++)
            #pragma unroll
            for (int j = 0; j < 4; j++)
                wmma::store_matrix_sync(stg + i*16*64 + j*16, acc[i][j], 64,
                                        wmma::mem_row_major);
        __syncwarp();
        const int r0 = bm + wm*32;
        const int c0 = bn + wn*64;
        #pragma unroll
        for (int idx = lane; idx < 512; idx += 32) {
            int r  = idx >> 4;
            int cq = (idx & 15) * 4;
            float4 v = *(float4*)&stg[r*64 + cq];
            v.x = softplusf(v.x + bias[c0 + cq + 0]);
            v.y = softplusf(v.y + bias[c0 + cq + 1]);
            v.z = softplusf(v.z + bias[c0 + cq + 2]);
            v.w = softplusf(v.w + bias[c0 + cq + 3]);
            *(float4*)&C[(size_t)(r0 + r) * ldc + c0 + cq] = v;
        }
    }
}

// ---------------- split-K reduce for params GEMM (+ fused d_low split) --------
// Also emits the compact bf16 hi/lo split of d_low (params[:, :DR]) directly.
__global__ void reduce_params_kernel()
{
    int i = blockIdx.x * blockDim.x + threadIdx.x;
    if (i >= MROWS * NPAR) return;
    float s = 0.f;
    #pragma unroll
    for (int z = 0; z < SPLITK2; z++)
        s += g_ppart[(size_t)z * MROWS * NPAR + i];
    g_params[i] = s;
    int r = i / NPAR, c = i - r * NPAR;
    if (c < DR) {
        __nv_bfloat16 hh = __float2bfloat16(s);
        g_ah[r * DR + c] = hh;
        g_al[r * DR + c] = __float2bfloat16(s - __bfloat162float(hh));
    }
}

// ---------------- fp32 -> bf16 hi/lo split (vectorized) ----------------------
__global__ void split_flat4(const float4* __restrict__ src,
                            __nv_bfloat162* __restrict__ h,
                            __nv_bfloat162* __restrict__ l, int n4)
{
    int i = blockIdx.x * blockDim.x + threadIdx.x;
    if (i >= n4) return;
    float4 v = src[i];
    __nv_bfloat162 h0 = __floats2bfloat162_rn(v.x, v.y);
    __nv_bfloat162 h1 = __floats2bfloat162_rn(v.z, v.w);
    float rx = v.x - __bfloat162float(h0.x);
    float ry = v.y - __bfloat162float(h0.y);
    float rz = v.z - __bfloat162float(h1.x);
    float rw = v.w - __bfloat162float(h1.y);
    h[i*2]   = h0;  h[i*2+1] = h1;
    l[i*2]   = __floats2bfloat162_rn(rx, ry);
    l[i*2+1] = __floats2bfloat162_rn(rz, rw);
}

// ---------------- depthwise causal conv (k=4) + SiLU (+ bf16 split) ----------
// 8 timesteps per thread: carry x[t-1..t-3] in registers (loads/output ~1.4 vs 4).
#define CONVT 8
__global__ void conv_silu_kernel(const float* __restrict__ conv_w)
{
    int i = blockIdx.x * blockDim.x + threadIdx.x;   // over (MROWS/CONVT)*INNER
    if (i >= MROWS / CONVT * INNER) return;
    int d  = i & (INNER - 1);
    int mb = i >> 11;                 // 0..511
    int m0 = mb * CONVT;
    int t0 = m0 & (LDIM - 1);
    float w0 = conv_w[d*4+0], w1 = conv_w[d*4+1];
    float w2 = conv_w[d*4+2], w3 = conv_w[d*4+3];
    const float* col = g_xz + (size_t)m0 * NXZ + d;
    float xm1, xm2, xm3;
    if (t0 == 0) { xm1 = xm2 = xm3 = 0.f; }
    else { xm1 = col[-NXZ]; xm2 = col[-2*NXZ]; xm3 = col[-3*NXZ]; }
    #pragma unroll
    for (int tt = 0; tt < CONVT; tt++) {
        float xc  = col[tt * NXZ];
        float acc = xc * w3;
        acc = fmaf(xm1, w2, acc);
        acc = fmaf(xm2, w1, acc);
        acc = fmaf(xm3, w0, acc);
        float s = acc * __fdividef(1.f, 1.f + __expf(-acc));
        int idx = (m0 + tt) * INNER + d;
        g_u[idx] = s;
        __nv_bfloat16 hh = __float2bfloat16(s);
        g_uh[idx] = hh;
        g_ul[idx] = __float2bfloat16(s - __bfloat162float(hh));
        xm3 = xm2; xm2 = xm1; xm1 = xc;
    }
}

// ---------------- segmented SSM scan ------------------------------------------
#define SCHUNK 16

__global__ void __launch_bounds__(128) scanA_kernel(const float* __restrict__ logA)
{
    __shared__ float s_u [SCHUNK*128];
    __shared__ float s_dt[SCHUNK*128];
    __shared__ float s_b [SCHUNK*16];

    const int tid = threadIdx.x;
    const int b   = blockIdx.y;
    const int seg = blockIdx.z;
    const int d0  = blockIdx.x * 128;
    const int d   = d0 + tid;
    const int bd  = b * INNER + d;

    float a[NST];
    bool fast = true;
    #pragma unroll
    for (int n = 0; n < NST; n++) {
        a[n] = -__expf(logA[d * NST + n]);
        fast = fast && (fabsf(a[n] + (float)(n + 1)) <= 2e-5f * (float)(n + 1));
    }
    float h[NST];
    #pragma unroll
    for (int n = 0; n < NST; n++) h[n] = 0.f;
    float sumdt = 0.f;

    for (int t0 = 0; t0 < SEGLEN; t0 += SCHUNK) {
        const int rowbase = b * LDIM + seg * SEGLEN + t0;
        #pragma unroll
        for (int r = 0; r < 4; r++) {
            int j = tid + r * 128;
            int row = j >> 5;
            int c   = (j & 31) * 4;
            int gidx = (rowbase + row) * INNER + d0 + c;
            *(float4*)&s_u [row*128 + c] = *(const float4*)&g_u [gidx];
            *(float4*)&s_dt[row*128 + c] = *(const float4*)&g_dt[gidx];
        }
        if (tid < 64) {
            int row = tid >> 2;
            int c   = (tid & 3) * 4;
            *(float4*)&s_b[row*16 + c] =
                *(const float4*)&g_params[(rowbase + row) * NPAR + DR + c];
        }
        __syncthreads();

        if (fast) {
            #pragma unroll 4
            for (int tt = 0; tt < SCHUNK; tt++) {
                float dtv = s_dt[tt*128 + tid];
                float du  = dtv * s_u[tt*128 + tid];
                float e1  = __expf(-dtv);
                float dec = e1;
                sumdt += dtv;
                #pragma unroll
                for (int n = 0; n < NST; n++) {
                    h[n] = fmaf(dec, h[n], du * s_b[tt*16 + n]);
                    dec *= e1;
                }
            }
        } else {
            for (int tt = 0; tt < SCHUNK; tt++) {
                float dtv = s_dt[tt*128 + tid];
                float du  = dtv * s_u[tt*128 + tid];
                sumdt += dtv;
                #pragma unroll
                for (int n = 0; n < NST; n++)
                    h[n] = fmaf(__expf(dtv * a[n]), h[n], du * s_b[tt*16 + n]);
            }
        }
        __syncthreads();
    }

    #pragma unroll
    for (int n = 0; n < NST; n++)
        g_hloc[((size_t)seg * NST + n) * MROWS + bd] = h[n];
    g_sumdt[(size_t)seg * MROWS + bd] = sumdt;
}

__global__ void __launch_bounds__(128) scan_combine(const float* __restrict__ logA)
{
    const int bd = blockIdx.x * 128 + threadIdx.x;   // 0..4095
    const int d  = bd & (INNER - 1);
    float a[NST];
    #pragma unroll
    for (int n = 0; n < NST; n++) a[n] = -__expf(logA[d * NST + n]);
    float h[NST];
    #pragma unroll
    for (int n = 0; n < NST; n++) h[n] = 0.f;
    for (int s = 0; s < SSEG; s++) {
        #pragma unroll
        for (int n = 0; n < NST; n++)
            g_hin[((size_t)s * NST + n) * MROWS + bd] = h[n];
        float sd = g_sumdt[(size_t)s * MROWS + bd];
        #pragma unroll
        for (int n = 0; n < NST; n++)
            h[n] = fmaf(__expf(a[n] * sd), h[n],
                        g_hloc[((size_t)s * NST + n) * MROWS + bd]);
    }
}

__global__ void __launch_bounds__(128) scanB_kernel(
    const float* __restrict__ logA, const float* __restrict__ Dvec)
{
    __shared__ float s_u [SCHUNK*128];
    __shared__ float s_dt[SCHUNK*128];
    __shared__ float s_g [SCHUNK*128];
    __shared__ float s_bc[SCHUNK*32];

    const int tid = threadIdx.x;
    const int b   = blockIdx.y;
    const int seg = blockIdx.z;
    const int d0  = blockIdx.x * 128;
    const int d   = d0 + tid;
    const int bd  = b * INNER + d;

    float a[NST];
    bool fast = true;
    #pragma unroll
    for (int n = 0; n < NST; n++) {
        a[n] = -__expf(logA[d * NST + n]);
        fast = fast && (fabsf(a[n] + (float)(n + 1)) <= 2e-5f * (float)(n + 1));
    }
    const float Dd = Dvec[d];
    float h[NST];
    #pragma unroll
    for (int n = 0; n < NST; n++)
        h[n] = g_hin[((size_t)seg * NST + n) * MROWS + bd];

    for (int t0 = 0; t0 < SEGLEN; t0 += SCHUNK) {
        const int rowbase = b * LDIM + seg * SEGLEN + t0;
        #pragma unroll
        for (int r = 0; r < 4; r++) {
            int j = tid + r * 128;
            int row = j >> 5;
            int c   = (j & 31) * 4;
            int gidx = (rowbase + row) * INNER + d0 + c;
            *(float4*)&s_u [row*128 + c] = *(const float4*)&g_u [gidx];
            *(float4*)&s_dt[row*128 + c] = *(const float4*)&g_dt[gidx];
            *(float4*)&s_g [row*128 + c] =
                *(const float4*)&g_xz[(size_t)(rowbase + row) * NXZ + INNER + d0 + c];
        }
        {
            int row = tid >> 3;
            int c   = (tid & 7) * 4;
            *(float4*)&s_bc[row*32 + c] =
                *(const float4*)&g_params[(rowbase + row) * NPAR + DR + c];
        }
        __syncthreads();

        if (fast) {
            #pragma unroll 4
            for (int tt = 0; tt < SCHUNK; tt++) {
                float dtv = s_dt[tt*128 + tid];
                float uu  = s_u [tt*128 + tid];
                float du  = dtv * uu;
                float e1  = __expf(-dtv);
                float dec = e1;
                float y = 0.f;
                #pragma unroll
                for (int n = 0; n < NST; n++) {
                    h[n] = fmaf(dec, h[n], du * s_bc[tt*32 + n]);
                    y    = fmaf(h[n], s_bc[tt*32 + 16 + n], y);
                    dec *= e1;
                }
                float g  = s_g[tt*128 + tid];
                float sg = g * __fdividef(1.f, 1.f + __expf(-g));
                float v  = fmaf(uu, Dd, y) * sg;
                int idx  = (rowbase + tt) * INNER + d;
                __nv_bfloat16 hh = __float2bfloat16(v);
                g_uh[idx] = hh;
                g_ul[idx] = __float2bfloat16(v - __bfloat162float(hh));
            }
        } else {
            for (int tt = 0; tt < SCHUNK; tt++) {
                float dtv = s_dt[tt*128 + tid];
                float uu  = s_u [tt*128 + tid];
                float du  = dtv * uu;
                float y = 0.f;
                #pragma unroll
                for (int n = 0; n < NST; n++) {
                    h[n] = fmaf(__expf(dtv * a[n]), h[n], du * s_bc[tt*32 + n]);
                    y    = fmaf(h[n], s_bc[tt*32 + 16 + n], y);
                }
                float g  = s_g[tt*128 + tid];
                float sg = g * __fdividef(1.f, 1.f + __expf(-g));
                float v  = fmaf(uu, Dd, y) * sg;
                int idx  = (rowbase + tt) * INNER + d;
                __nv_bfloat16 hh = __float2bfloat16(v);
                g_uh[idx] = hh;
                g_ul[idx] = __float2bfloat16(v - __bfloat162float(hh));
            }
        }
        __syncthreads();
    }
}

// ---------------- launcher ----------------------------------------------------
extern "C" void kernel_launch(void* const* d_in, const int* in_sizes, int n_in,
                              void* d_out, int out_size)
{
    const float* x      = (const float*)d_in[0];  // (2,2048,1024)
    const float* W_in   = (const float*)d_in[1];  // (4096,1024)
    const float* conv_w = (const float*)d_in[2];  // (2048,4)
    const float* W_ssm  = (const float*)d_in[3];  // (96,2048)
    const float* W_dt   = (const float*)d_in[4];  // (2048,64)
    const float* b_dt   = (const float*)d_in[5];  // (2048,)
    const float* logA   = (const float*)d_in[6];  // (2048,16)
    const float* Dv     = (const float*)d_in[7];  // (2048,)
    const float* W_out  = (const float*)d_in[8];  // (1024,2048)
    float* out = (float*)d_out;

    float *xz, *params, *ppart, *dtb;
    __nv_bfloat16 *ah, *al, *bh, *bl, *wdh, *wdl, *uh, *ul;
    cudaGetSymbolAddress((void**)&xz,     g_xz);
    cudaGetSymbolAddress((void**)&params, g_params);
    cudaGetSymbolAddress((void**)&ppart,  g_ppart);
    cudaGetSymbolAddress((void**)&dtb,    g_dt);
    cudaGetSymbolAddress((void**)&ah,  g_ah);
    cudaGetSymbolAddress((void**)&al,  g_al);
    cudaGetSymbolAddress((void**)&bh,  g_bh);
    cudaGetSymbolAddress((void**)&bl,  g_bl);
    cudaGetSymbolAddress((void**)&wdh, g_wdh);
    cudaGetSymbolAddress((void**)&wdl, g_wdl);
    cudaGetSymbolAddress((void**)&uh,  g_uh);
    cudaGetSymbolAddress((void**)&ul,  g_ul);

    cudaFuncSetAttribute(gemm_wmma<0>,
        cudaFuncAttributeMaxDynamicSharedMemorySize, GEMM_SMEM);
    cudaFuncSetAttribute(gemm_wmma<1>,
        cudaFuncAttributeMaxDynamicSharedMemorySize, GEMM_SMEM);

    // 0-2) splits (x, W_in, W_dt) — gemm1 lands at launch idx 3 for ncu
    split_flat4<<<(MROWS*MDL/4 + 255)/256, 256>>>(
        (const float4*)x, (__nv_bfloat162*)ah, (__nv_bfloat162*)al, MROWS*MDL/4);
    split_flat4<<<(NXZ*MDL/4 + 255)/256, 256>>>(
        (const float4*)W_in, (__nv_bfloat162*)bh, (__nv_bfloat162*)bl, NXZ*MDL/4);
    split_flat4<<<(INNER*DR/4 + 255)/256, 256>>>(
        (const float4*)W_dt, (__nv_bfloat162*)wdh, (__nv_bfloat162*)wdl, INNER*DR/4);

    // 3) xz = x @ W_in^T  (M=4096, N=4096, K=1024)
    gemm_wmma<0><<<dim3(NXZ/128, MROWS/128, 1), 256, GEMM_SMEM>>>(
        ah, al, bh, bl, xz, NXZ, NXZ, MDL, MDL, 0, nullptr);

    // 4) depthwise causal conv + silu -> u (fp32 + bf16 split)
    conv_silu_kernel<<<(MROWS/CONVT*INNER + 255)/256, 256>>>(conv_w);

    // 5) split W_ssm (reuses bh/bl)
    split_flat4<<<(NPAR*INNER/4 + 255)/256, 256>>>(
        (const float4*)W_ssm, (__nv_bfloat162*)bh, (__nv_bfloat162*)bl, NPAR*INNER/4);

    // 6-7) params = u @ W_ssm^T  (M=4096, N=96, K=2048), split-K=8 + reduce
    //      (reduce also emits the compact d_low bf16 split into ah/al)
    gemm_wmma<0><<<dim3(1, MROWS/128, SPLITK2), 256, GEMM_SMEM>>>(
        uh, ul, bh, bl, ppart, NPAR, NPAR, INNER/SPLITK2, INNER,
        (size_t)MROWS*NPAR, nullptr);
    reduce_params_kernel<<<(MROWS*NPAR + 255)/256, 256>>>();

    // 8) dt = softplus(d_low @ W_dt^T + b_dt)  (M=4096, N=2048, K=64)
    gemm_wmma<1><<<dim3(INNER/128, MROWS/128, 1), 256, GEMM_SMEM>>>(
        ah, al, wdh, wdl, dtb, INNER, INNER, DR, DR, 0, b_dt);

    // 9-11) segmented SSM scan (S=16): passA, combine, passB
    scanA_kernel<<<dim3(INNER/128, BDIM, SSEG), 128>>>(logA);
    scan_combine<<<MROWS/128, 128>>>(logA);
    scanB_kernel<<<dim3(INNER/128, BDIM, SSEG), 128>>>(logA, Dv);

    // 12) split W_out (reuses bh/bl)
    split_flat4<<<(MDL*INNER/4 + 255)/256, 256>>>(
        (const float4*)W_out, (__nv_bfloat162*)bh, (__nv_bfloat162*)bl, MDL*INNER/4);

    // 13) out = ys @ W_out^T  (M=4096, N=1024, K=2048)
    gemm_wmma<0><<<dim3(MDL/128, MROWS/128, 1), 256, GEMM_SMEM>>>(
        uh, ul, bh, bl, out, MDL, MDL, INNER, INNER, 0, nullptr);
}